// round 4
// baseline (speedup 1.0000x reference)
#include <cuda_runtime.h>

#define N_NODE 50000
#define N_EDGE 800000
#define D 64
#define C 40
#define CDIV(a,b) (((a)+(b)-1)/(b))

// ---------------- scratch (static device arrays; no allocs) ----------------
__device__ __align__(16) float g_xw[N_NODE * D];   // x @ W1
__device__ __align__(16) float g_h[N_NODE * D];    // layer-1 output (post relu)
__device__ __align__(16) float g_agg[N_NODE * D];  // layer-1 neighborhood sum
__device__ __align__(16) float g_hw[N_NODE * C];   // h @ W2
__device__ float g_inv[N_NODE];     // 1/max(||feat||,1e-12)
__device__ float g_rs[N_NODE];      // segment_sum(sim, row)
__device__ float g_cnt[N_NODE];     // #kept edges per row
__device__ float g_degw[N_NODE];    // segment_sum(w_edge, row)
__device__ float g_wself[N_NODE];   // exp(1/(deg+1))
__device__ float g_dinv[N_NODE];    // 1/sqrt(deg_total)
__device__ float g_selfc[N_NODE];   // w_self * dinv^2
__device__ float g_sim[N_EDGE];
__device__ float g_wedge[N_EDGE];

// ---------------- kernels ----------------

// warp per node: inv-norm of feat, zero per-node accumulators, zero g_agg row
__global__ void k_prep(const float* __restrict__ feat) {
    int t = blockIdx.x * blockDim.x + threadIdx.x;
    int u = t >> 5, lane = t & 31;
    if (u >= N_NODE) return;
    float v0 = feat[u * D + lane];
    float v1 = feat[u * D + lane + 32];
    g_agg[u * D + lane] = 0.f;
    g_agg[u * D + lane + 32] = 0.f;
    float s = v0 * v0 + v1 * v1;
    #pragma unroll
    for (int o = 16; o; o >>= 1) s += __shfl_xor_sync(~0u, s, o);
    if (lane == 0) {
        g_inv[u] = 1.f / fmaxf(sqrtf(s), 1e-12f);
        g_rs[u] = 0.f; g_cnt[u] = 0.f; g_degw[u] = 0.f;
    }
}

// 16 lanes per edge: cosine sim, threshold, accumulate rs/cnt
// edge_index is int32 (JAX default config downcasts the int64 request)
__global__ void k_sim(const float* __restrict__ feat, const int* __restrict__ ei) {
    int t = blockIdx.x * blockDim.x + threadIdx.x;
    int e = t >> 4, lane = t & 15;
    int r = ei[e];
    int c = ei[N_EDGE + e];
    const float4* f4 = (const float4*)feat;
    float4 a = f4[r * 16 + lane];
    float4 b = f4[c * 16 + lane];
    float s = a.x * b.x + a.y * b.y + a.z * b.z + a.w * b.w;
    s += __shfl_xor_sync(~0u, s, 8);
    s += __shfl_xor_sync(~0u, s, 4);
    s += __shfl_xor_sync(~0u, s, 2);
    s += __shfl_xor_sync(~0u, s, 1);
    s *= g_inv[r] * g_inv[c];
    if (s < 0.1f) s = 0.f;
    if (lane == 0) {
        g_sim[e] = s;
        if (s > 0.f) {
            atomicAdd(&g_rs[r], s);
            atomicAdd(&g_cnt[r], 1.f);
        }
    }
}

__global__ void k_nodew() {
    int u = blockIdx.x * blockDim.x + threadIdx.x;
    if (u < N_NODE) g_wself[u] = expf(1.f / (g_cnt[u] + 1.f));
}

// thread per edge: w_edge = exp(sim/rs[row]); accumulate weighted degree
__global__ void k_edgew(const int* __restrict__ ei) {
    int e = blockIdx.x * blockDim.x + threadIdx.x;
    if (e >= N_EDGE) return;
    float s = g_sim[e];
    float w = 0.f;
    if (s > 0.f) {
        int r = ei[e];
        w = expf(s / fmaxf(g_rs[r], 1e-12f));
        atomicAdd(&g_degw[r], w);
    }
    g_wedge[e] = w;
}

__global__ void k_dinv() {
    int u = blockIdx.x * blockDim.x + threadIdx.x;
    if (u >= N_NODE) return;
    float deg = g_degw[u] + g_wself[u];
    float di = rsqrtf(fmaxf(deg, 1e-12f));
    g_dinv[u] = di;
    g_selfc[u] = g_wself[u] * di * di;
}

// GEMM: Y[N, FOUT] = X[N, 64] @ W[64, FOUT]; thread computes 4 consecutive outputs
template <int FOUT, int NPB>
__global__ void k_gemm(const float* __restrict__ X, const float* __restrict__ W,
                       float* __restrict__ Y) {
    constexpr int Q = FOUT / 4;
    __shared__ float4 sW[64 * Q];
    __shared__ float  sX[NPB * 64];
    int tid = threadIdx.x;
    const float4* W4 = (const float4*)W;
    for (int i = tid; i < 64 * Q; i += blockDim.x) sW[i] = W4[i];
    int base = blockIdx.x * NPB;
    for (int i = tid; i < NPB * 64; i += blockDim.x) {
        int n = base + i / 64;
        sX[i] = (n < N_NODE) ? X[n * 64 + (i & 63)] : 0.f;
    }
    __syncthreads();
    int ni = tid / Q, q = tid - ni * Q;
    int n = base + ni;
    if (n >= N_NODE) return;
    float4 acc = {0.f, 0.f, 0.f, 0.f};
    #pragma unroll
    for (int k = 0; k < 64; k++) {
        float xv = sX[ni * 64 + k];
        float4 w = sW[k * Q + q];
        acc.x += xv * w.x; acc.y += xv * w.y;
        acc.z += xv * w.z; acc.w += xv * w.w;
    }
    ((float4*)Y)[n * Q + q] = acc;
}

// 16 lanes per edge: scatter coef * H[col] into O[row] via vector red
template <int Q>
__global__ void k_agg(const float* __restrict__ H, float* __restrict__ O,
                      const int* __restrict__ ei) {
    int t = blockIdx.x * blockDim.x + threadIdx.x;
    int e = t >> 4, lane = t & 15;
    if (e >= N_EDGE) return;
    float w = g_wedge[e];
    if (w == 0.f) return;   // ~79% pruned in layer 1
    int r = ei[e], c = ei[N_EDGE + e];
    float coef = w * g_dinv[r] * g_dinv[c];
    if (lane < Q) {
        float4 v = ((const float4*)H)[c * Q + lane];
        float4* o = (float4*)O + (size_t)r * Q + lane;
        asm volatile("red.global.add.v4.f32 [%0], {%1,%2,%3,%4};"
                     :: "l"(o), "f"(coef * v.x), "f"(coef * v.y),
                        "f"(coef * v.z), "f"(coef * v.w)
                     : "memory");
    }
}

// finalize layer 1: +self term +b1, relu, inv-norm of h, re-zero accumulators,
// zero the layer-2 output accumulator (d_out)
__global__ void k_fin1(const float* __restrict__ b1, float* __restrict__ O) {
    int t = blockIdx.x * blockDim.x + threadIdx.x;
    int u = t >> 5, lane = t & 31;
    if (u >= N_NODE) return;
    float sc = g_selfc[u];
    float v0 = g_agg[u * D + lane]      + sc * g_xw[u * D + lane]      + b1[lane];
    float v1 = g_agg[u * D + lane + 32] + sc * g_xw[u * D + lane + 32] + b1[lane + 32];
    v0 = fmaxf(v0, 0.f);
    v1 = fmaxf(v1, 0.f);
    g_h[u * D + lane] = v0;
    g_h[u * D + lane + 32] = v1;
    O[(size_t)u * C + lane] = 0.f;
    if (lane < 8) O[(size_t)u * C + 32 + lane] = 0.f;
    float s = v0 * v0 + v1 * v1;
    #pragma unroll
    for (int o = 16; o; o >>= 1) s += __shfl_xor_sync(~0u, s, o);
    if (lane == 0) {
        g_inv[u] = 1.f / fmaxf(sqrtf(s), 1e-12f);
        g_rs[u] = 0.f; g_cnt[u] = 0.f; g_degw[u] = 0.f;
    }
}

// finalize layer 2: +self +b2, log_softmax over 40 classes (warp per node)
__global__ void k_fin2(const float* __restrict__ b2, float* __restrict__ O) {
    int t = blockIdx.x * blockDim.x + threadIdx.x;
    int u = t >> 5, lane = t & 31;
    if (u >= N_NODE) return;
    float sc = g_selfc[u];
    size_t base = (size_t)u * C;
    float v0 = O[base + lane] + sc * g_hw[u * C + lane] + b2[lane];
    float v1 = -1e30f;
    if (lane < 8)
        v1 = O[base + 32 + lane] + sc * g_hw[u * C + 32 + lane] + b2[32 + lane];
    float m = fmaxf(v0, v1);
    #pragma unroll
    for (int o = 16; o; o >>= 1) m = fmaxf(m, __shfl_xor_sync(~0u, m, o));
    float s = expf(v0 - m) + ((lane < 8) ? expf(v1 - m) : 0.f);
    #pragma unroll
    for (int o = 16; o; o >>= 1) s += __shfl_xor_sync(~0u, s, o);
    float lse = m + logf(s);
    O[base + lane] = v0 - lse;
    if (lane < 8) O[base + 32 + lane] = v1 - lse;
}

// ---------------- launch ----------------
extern "C" void kernel_launch(void* const* d_in, const int* in_sizes, int n_in,
                              void* d_out, int out_size) {
    const float* x  = (const float*)d_in[0];
    const int*   ei = (const int*)d_in[1];   // int32! (JAX default x64-disabled)
    const float* W1 = (const float*)d_in[2];
    const float* b1 = (const float*)d_in[3];
    const float* W2 = (const float*)d_in[4];
    const float* b2 = (const float*)d_in[5];
    float* out = (float*)d_out;

    float *p_h, *p_xw, *p_hw, *p_agg;
    cudaGetSymbolAddress((void**)&p_h,  g_h);
    cudaGetSymbolAddress((void**)&p_xw, g_xw);
    cudaGetSymbolAddress((void**)&p_hw, g_hw);
    cudaGetSymbolAddress((void**)&p_agg, g_agg);

    const int T = 256;

    // ---- layer 1 (attention on x) ----
    k_prep<<<CDIV(N_NODE * 32, T), T>>>(x);
    k_sim<<<CDIV(N_EDGE * 16, T), T>>>(x, ei);
    k_nodew<<<CDIV(N_NODE, T), T>>>();
    k_edgew<<<CDIV(N_EDGE, T), T>>>(ei);
    k_dinv<<<CDIV(N_NODE, T), T>>>();
    k_gemm<64, 16><<<CDIV(N_NODE, 16), 256>>>(x, W1, p_xw);
    k_agg<16><<<CDIV(N_EDGE * 16, T), T>>>(p_xw, p_agg, ei);
    k_fin1<<<CDIV(N_NODE * 32, T), T>>>(b1, out);

    // ---- layer 2 (attention on h) ----
    k_sim<<<CDIV(N_EDGE * 16, T), T>>>(p_h, ei);
    k_nodew<<<CDIV(N_NODE, T), T>>>();
    k_edgew<<<CDIV(N_EDGE, T), T>>>(ei);
    k_dinv<<<CDIV(N_NODE, T), T>>>();
    k_gemm<40, 24><<<CDIV(N_NODE, 24), 240>>>(p_h, W2, p_hw);
    k_agg<10><<<CDIV(N_EDGE * 16, T), T>>>(p_hw, out, ei);
    k_fin2<<<CDIV(N_NODE * 32, T), T>>>(b2, out);
}

// round 6
// speedup vs baseline: 1.1034x; 1.1034x over previous
#include <cuda_runtime.h>

#define N_NODE 50000
#define N_EDGE 800000
#define D 64
#define C 40
#define CDIV(a,b) (((a)+(b)-1)/(b))
#define SCAN_B 512
#define NBLK 98          // CDIV(N_NODE, SCAN_B)

// ---------------- scratch (static device arrays; no allocs) ----------------
__device__ __align__(16) float g_xw[N_NODE * D];   // x @ W1
__device__ __align__(16) float g_h[N_NODE * D];    // layer-1 output (post relu)
__device__ __align__(16) float g_hw[N_NODE * C];   // h @ W2
__device__ float g_inv[N_NODE];     // 1/max(||feat||,1e-12)
__device__ float g_dinv[N_NODE];    // 1/sqrt(deg_total)
__device__ float g_selfc[N_NODE];   // w_self * dinv^2
__device__ int   g_hist[N_NODE];    // per-row edge count
__device__ int   g_start[N_NODE];   // CSR row start (exclusive scan of hist)
__device__ int   g_pos[N_NODE];     // scatter cursor
__device__ int   g_bsum[NBLK];
__device__ int   g_boff[NBLK];
__device__ int   g_csrcol[N_EDGE];  // col, CSR order
__device__ int   g_epos[N_EDGE];    // edge id -> CSR position
__device__ float g_simc[N_EDGE];    // sim, CSR order
__device__ float g_w[N_EDGE];       // w_edge, CSR order

// ---------------- CSR build ----------------

// warp per node: inv-norm of x; zero histogram
__global__ void k_prep(const float* __restrict__ feat) {
    int t = blockIdx.x * blockDim.x + threadIdx.x;
    int u = t >> 5, lane = t & 31;
    if (u >= N_NODE) return;
    float v0 = feat[u * D + lane];
    float v1 = feat[u * D + lane + 32];
    float s = v0 * v0 + v1 * v1;
    #pragma unroll
    for (int o = 16; o; o >>= 1) s += __shfl_xor_sync(~0u, s, o);
    if (lane == 0) {
        g_inv[u] = 1.f / fmaxf(sqrtf(s), 1e-12f);
        g_hist[u] = 0;
    }
}

__global__ void k_hist(const int* __restrict__ ei) {
    int e = blockIdx.x * blockDim.x + threadIdx.x;
    if (e < N_EDGE) atomicAdd(&g_hist[ei[e]], 1);
}

// block-level exclusive scan of hist (512/block), block totals to g_bsum
__global__ void k_scanA() {
    __shared__ int wsum[16];
    int i = blockIdx.x * SCAN_B + threadIdx.x;
    int lane = threadIdx.x & 31, wid = threadIdx.x >> 5;
    int v = (i < N_NODE) ? g_hist[i] : 0;
    int inc = v;
    #pragma unroll
    for (int o = 1; o < 32; o <<= 1) {
        int t = __shfl_up_sync(~0u, inc, o);
        if (lane >= o) inc += t;
    }
    if (lane == 31) wsum[wid] = inc;
    __syncthreads();
    if (wid == 0) {
        int s = (lane < 16) ? wsum[lane] : 0;
        #pragma unroll
        for (int o = 1; o < 16; o <<= 1) {
            int t = __shfl_up_sync(~0u, s, o);
            if (lane >= o) s += t;
        }
        if (lane < 16) wsum[lane] = s;
    }
    __syncthreads();
    int off = wid ? wsum[wid - 1] : 0;
    if (i < N_NODE) g_start[i] = off + inc - v;
    if (threadIdx.x == SCAN_B - 1) g_bsum[blockIdx.x] = off + inc;
}

// scan the 98 block sums (one block, 128 threads)
__global__ void k_scanB() {
    __shared__ int wsum[4];
    int i = threadIdx.x;
    int lane = i & 31, wid = i >> 5;
    int v = (i < NBLK) ? g_bsum[i] : 0;
    int inc = v;
    #pragma unroll
    for (int o = 1; o < 32; o <<= 1) {
        int t = __shfl_up_sync(~0u, inc, o);
        if (lane >= o) inc += t;
    }
    if (lane == 31) wsum[wid] = inc;
    __syncthreads();
    if (wid == 0) {
        int s = (lane < 4) ? wsum[lane] : 0;
        #pragma unroll
        for (int o = 1; o < 4; o <<= 1) {
            int t = __shfl_up_sync(~0u, s, o);
            if (lane >= o) s += t;
        }
        if (lane < 4) wsum[lane] = s;
    }
    __syncthreads();
    int off = wid ? wsum[wid - 1] : 0;
    if (i < NBLK) g_boff[i] = off + inc - v;
}

__global__ void k_scanC() {
    int i = blockIdx.x * SCAN_B + threadIdx.x;
    if (i < N_NODE) {
        int s = g_start[i] + g_boff[blockIdx.x];
        g_start[i] = s;
        g_pos[i] = s;
    }
}

__global__ void k_scatter(const int* __restrict__ ei) {
    int e = blockIdx.x * blockDim.x + threadIdx.x;
    if (e >= N_EDGE) return;
    int r = ei[e];
    int p = atomicAdd(&g_pos[r], 1);
    g_csrcol[p] = ei[N_EDGE + e];
    g_epos[e] = p;
}

// ---------------- per-layer kernels ----------------

// 16 lanes per edge: cosine sim, threshold, store in CSR order. No atomics.
__global__ void k_sim(const float* __restrict__ feat, const int* __restrict__ ei) {
    int t = blockIdx.x * blockDim.x + threadIdx.x;
    int e = t >> 4, lane = t & 15;
    int r = ei[e];
    int c = ei[N_EDGE + e];
    const float4* f4 = (const float4*)feat;
    float4 a = f4[r * 16 + lane];
    float4 b = f4[c * 16 + lane];
    float s = a.x * b.x + a.y * b.y + a.z * b.z + a.w * b.w;
    s += __shfl_xor_sync(~0u, s, 8);
    s += __shfl_xor_sync(~0u, s, 4);
    s += __shfl_xor_sync(~0u, s, 2);
    s += __shfl_xor_sync(~0u, s, 1);
    s *= g_inv[r] * g_inv[c];
    if (s < 0.1f) s = 0.f;
    if (lane == 0) g_simc[g_epos[e]] = s;
}

// warp per row: rs/cnt, w_edge, degw, dinv, selfc — all from contiguous CSR data
__global__ void k_row() {
    int t = blockIdx.x * blockDim.x + threadIdx.x;
    int u = t >> 5, lane = t & 31;
    if (u >= N_NODE) return;
    int st = g_start[u], n = g_hist[u];
    float rs = 0.f; float k = 0.f;
    for (int i = lane; i < n; i += 32) {
        float s = g_simc[st + i];
        rs += s;
        if (s > 0.f) k += 1.f;
    }
    #pragma unroll
    for (int o = 16; o; o >>= 1) {
        rs += __shfl_xor_sync(~0u, rs, o);
        k  += __shfl_xor_sync(~0u, k, o);
    }
    float wself = expf(1.f / (k + 1.f));
    float inv_rs = 1.f / fmaxf(rs, 1e-12f);
    float degw = 0.f;
    for (int i = lane; i < n; i += 32) {
        float s = g_simc[st + i];
        float w = (s > 0.f) ? expf(s * inv_rs) : 0.f;
        g_w[st + i] = w;
        degw += w;
    }
    #pragma unroll
    for (int o = 16; o; o >>= 1) degw += __shfl_xor_sync(~0u, degw, o);
    if (lane == 0) {
        float di = rsqrtf(fmaxf(degw + wself, 1e-12f));
        g_dinv[u] = di;
        g_selfc[u] = wself * di * di;
    }
}

// GEMM: Y[N, FOUT] = X[N, 64] @ W[64, FOUT]
template <int FOUT, int NPB>
__global__ void k_gemm(const float* __restrict__ X, const float* __restrict__ W,
                       float* __restrict__ Y) {
    constexpr int Q = FOUT / 4;
    __shared__ float4 sW[64 * Q];
    __shared__ float  sX[NPB * 64];
    int tid = threadIdx.x;
    const float4* W4 = (const float4*)W;
    for (int i = tid; i < 64 * Q; i += blockDim.x) sW[i] = W4[i];
    int base = blockIdx.x * NPB;
    for (int i = tid; i < NPB * 64; i += blockDim.x) {
        int n = base + i / 64;
        sX[i] = (n < N_NODE) ? X[n * 64 + (i & 63)] : 0.f;
    }
    __syncthreads();
    int ni = tid / Q, q = tid - ni * Q;
    int n = base + ni;
    if (n >= N_NODE) return;
    float4 acc = {0.f, 0.f, 0.f, 0.f};
    #pragma unroll
    for (int k = 0; k < 64; k++) {
        float xv = sX[ni * 64 + k];
        float4 w = sW[k * Q + q];
        acc.x += xv * w.x; acc.y += xv * w.y;
        acc.z += xv * w.z; acc.w += xv * w.w;
    }
    ((float4*)Y)[n * Q + q] = acc;
}

// layer-1 aggregate, warp per row, 2 edges in flight; fused relu + h-norm epilogue
__global__ void k_agg1(const float* __restrict__ b1) {
    int t = blockIdx.x * blockDim.x + threadIdx.x;
    int u = t >> 5, lane = t & 31;
    if (u >= N_NODE) return;
    int sub = lane >> 4, q = lane & 15;
    int st = g_start[u], n = g_hist[u];
    const float4* H4 = (const float4*)g_xw;
    float4 acc = {0.f, 0.f, 0.f, 0.f};
    for (int i = sub; i < n; i += 2) {
        int p = st + i;
        float w = g_w[p];
        if (w != 0.f) {
            int c = g_csrcol[p];
            float coef = w * g_dinv[c];
            float4 v = H4[c * 16 + q];
            acc.x += coef * v.x; acc.y += coef * v.y;
            acc.z += coef * v.z; acc.w += coef * v.w;
        }
    }
    acc.x += __shfl_xor_sync(~0u, acc.x, 16);
    acc.y += __shfl_xor_sync(~0u, acc.y, 16);
    acc.z += __shfl_xor_sync(~0u, acc.z, 16);
    acc.w += __shfl_xor_sync(~0u, acc.w, 16);
    float dr = g_dinv[u], sc = g_selfc[u];
    float4 self = H4[u * 16 + q];
    float4 bq = ((const float4*)b1)[q];
    float4 o;
    o.x = fmaxf(dr * acc.x + sc * self.x + bq.x, 0.f);
    o.y = fmaxf(dr * acc.y + sc * self.y + bq.y, 0.f);
    o.z = fmaxf(dr * acc.z + sc * self.z + bq.z, 0.f);
    o.w = fmaxf(dr * acc.w + sc * self.w + bq.w, 0.f);
    if (lane < 16) ((float4*)g_h)[u * 16 + q] = o;
    // inv-norm of h for layer-2 attention (reduce over the 16-lane group)
    float s = o.x * o.x + o.y * o.y + o.z * o.z + o.w * o.w;
    s += __shfl_xor_sync(~0u, s, 8);
    s += __shfl_xor_sync(~0u, s, 4);
    s += __shfl_xor_sync(~0u, s, 2);
    s += __shfl_xor_sync(~0u, s, 1);
    if (lane == 0) g_inv[u] = 1.f / fmaxf(sqrtf(s), 1e-12f);
}

// layer-2 aggregate, warp per row; fused log-softmax epilogue
__global__ void k_agg2(const float* __restrict__ b2, float* __restrict__ O) {
    int t = blockIdx.x * blockDim.x + threadIdx.x;
    int u = t >> 5, lane = t & 31;
    if (u >= N_NODE) return;
    int sub = lane >> 4, q = lane & 15;
    bool act = q < 10;
    int st = g_start[u], n = g_hist[u];
    const float4* H4 = (const float4*)g_hw;
    float4 acc = {0.f, 0.f, 0.f, 0.f};
    for (int i = sub; i < n; i += 2) {
        int p = st + i;
        float w = g_w[p];
        if (w != 0.f && act) {
            int c = g_csrcol[p];
            float coef = w * g_dinv[c];
            float4 v = H4[c * 10 + q];
            acc.x += coef * v.x; acc.y += coef * v.y;
            acc.z += coef * v.z; acc.w += coef * v.w;
        }
    }
    acc.x += __shfl_xor_sync(~0u, acc.x, 16);
    acc.y += __shfl_xor_sync(~0u, acc.y, 16);
    acc.z += __shfl_xor_sync(~0u, acc.z, 16);
    acc.w += __shfl_xor_sync(~0u, acc.w, 16);
    float dr = g_dinv[u], sc = g_selfc[u];
    float4 o = {0.f, 0.f, 0.f, 0.f};
    if (act) {
        float4 self = H4[u * 10 + q];
        float4 bq = ((const float4*)b2)[q];
        o.x = dr * acc.x + sc * self.x + bq.x;
        o.y = dr * acc.y + sc * self.y + bq.y;
        o.z = dr * acc.z + sc * self.z + bq.z;
        o.w = dr * acc.w + sc * self.w + bq.w;
    }
    // log-softmax over 40 classes spread across the 10 active q-lanes
    float m = act ? fmaxf(fmaxf(o.x, o.y), fmaxf(o.z, o.w)) : -1e30f;
    m = fmaxf(m, __shfl_xor_sync(~0u, m, 8));
    m = fmaxf(m, __shfl_xor_sync(~0u, m, 4));
    m = fmaxf(m, __shfl_xor_sync(~0u, m, 2));
    m = fmaxf(m, __shfl_xor_sync(~0u, m, 1));
    float s = act ? (expf(o.x - m) + expf(o.y - m) + expf(o.z - m) + expf(o.w - m)) : 0.f;
    s += __shfl_xor_sync(~0u, s, 8);
    s += __shfl_xor_sync(~0u, s, 4);
    s += __shfl_xor_sync(~0u, s, 2);
    s += __shfl_xor_sync(~0u, s, 1);
    float lse = m + logf(s);
    if (lane < 16 && act) {
        float4 r = {o.x - lse, o.y - lse, o.z - lse, o.w - lse};
        ((float4*)O)[u * 10 + q] = r;
    }
}

// ---------------- launch ----------------
extern "C" void kernel_launch(void* const* d_in, const int* in_sizes, int n_in,
                              void* d_out, int out_size) {
    const float* x  = (const float*)d_in[0];
    const int*   ei = (const int*)d_in[1];   // int32 (JAX default x64-disabled)
    const float* W1 = (const float*)d_in[2];
    const float* b1 = (const float*)d_in[3];
    const float* W2 = (const float*)d_in[4];
    const float* b2 = (const float*)d_in[5];
    float* out = (float*)d_out;

    float *p_h, *p_xw, *p_hw;
    cudaGetSymbolAddress((void**)&p_h,  g_h);
    cudaGetSymbolAddress((void**)&p_xw, g_xw);
    cudaGetSymbolAddress((void**)&p_hw, g_hw);

    const int T = 256;

    // ---- CSR build (int atomics only) ----
    k_prep<<<CDIV(N_NODE * 32, T), T>>>(x);
    k_hist<<<CDIV(N_EDGE, T), T>>>(ei);
    k_scanA<<<NBLK, SCAN_B>>>();
    k_scanB<<<1, 128>>>();
    k_scanC<<<NBLK, SCAN_B>>>();
    k_scatter<<<CDIV(N_EDGE, T), T>>>(ei);

    // ---- layer 1 (attention on x) ----
    k_sim<<<CDIV(N_EDGE * 16, T), T>>>(x, ei);
    k_row<<<CDIV(N_NODE * 32, T), T>>>();
    k_gemm<64, 16><<<CDIV(N_NODE, 16), 256>>>(x, W1, p_xw);
    k_agg1<<<CDIV(N_NODE * 32, T), T>>>(b1);

    // ---- layer 2 (attention on h) ----
    k_sim<<<CDIV(N_EDGE * 16, T), T>>>(p_h, ei);
    k_row<<<CDIV(N_NODE * 32, T), T>>>();
    k_gemm<40, 24><<<CDIV(N_NODE, 24), 240>>>(p_h, W2, p_hw);
    k_agg2<<<CDIV(N_NODE * 32, T), T>>>(b2, out);
}

// round 10
// speedup vs baseline: 1.2549x; 1.1373x over previous
#include <cuda_runtime.h>

#define N_NODE 50000
#define N_EDGE 800000
#define D 64
#define C 40
#define CDIV(a,b) (((a)+(b)-1)/(b))
#define SCAN_B 512
#define NBLK 98          // CDIV(N_NODE, SCAN_B)

// ---------------- scratch (static device arrays; no allocs) ----------------
__device__ __align__(16) float g_xw[N_NODE * D];   // x @ W1
__device__ __align__(16) float g_h[N_NODE * D];    // layer-1 output (post relu)
__device__ __align__(16) float g_hw[N_NODE * C];   // h @ W2
__device__ float g_inv[N_NODE];     // 1/max(||feat||,1e-12)
__device__ float g_dinv[N_NODE];    // 1/sqrt(deg_total)
__device__ float g_selfc[N_NODE];   // w_self * dinv^2
__device__ int   g_hist[N_NODE];    // per-row edge count
__device__ int   g_start[N_NODE];   // CSR row start (exclusive scan of hist)
__device__ int   g_pos[N_NODE];     // scatter cursor
__device__ int   g_bsum[NBLK];
__device__ int   g_csrcol[N_EDGE];  // col, CSR order
__device__ float g_simc[N_EDGE];    // sim, CSR order
__device__ float g_w[N_EDGE];       // w_edge, CSR order

// ---------------- CSR build ----------------

// warp per node: inv-norm of x; zero histogram
__global__ void k_prep(const float* __restrict__ feat) {
    int t = blockIdx.x * blockDim.x + threadIdx.x;
    int u = t >> 5, lane = t & 31;
    if (u >= N_NODE) return;
    float v0 = feat[u * D + lane];
    float v1 = feat[u * D + lane + 32];
    float s = v0 * v0 + v1 * v1;
    #pragma unroll
    for (int o = 16; o; o >>= 1) s += __shfl_xor_sync(~0u, s, o);
    if (lane == 0) {
        g_inv[u] = 1.f / fmaxf(sqrtf(s), 1e-12f);
        g_hist[u] = 0;
    }
}

__global__ void k_hist(const int* __restrict__ ei) {
    int e = blockIdx.x * blockDim.x + threadIdx.x;
    if (e < N_EDGE) atomicAdd(&g_hist[ei[e]], 1);
}

// block-level exclusive scan of hist (512/block), block totals to g_bsum
__global__ void k_scanA() {
    __shared__ int wsum[16];
    int i = blockIdx.x * SCAN_B + threadIdx.x;
    int lane = threadIdx.x & 31, wid = threadIdx.x >> 5;
    int v = (i < N_NODE) ? g_hist[i] : 0;
    int inc = v;
    #pragma unroll
    for (int o = 1; o < 32; o <<= 1) {
        int t = __shfl_up_sync(~0u, inc, o);
        if (lane >= o) inc += t;
    }
    if (lane == 31) wsum[wid] = inc;
    __syncthreads();
    if (wid == 0) {
        int s = (lane < 16) ? wsum[lane] : 0;
        #pragma unroll
        for (int o = 1; o < 16; o <<= 1) {
            int t = __shfl_up_sync(~0u, s, o);
            if (lane >= o) s += t;
        }
        if (lane < 16) wsum[lane] = s;
    }
    __syncthreads();
    int off = wid ? wsum[wid - 1] : 0;
    if (i < N_NODE) g_start[i] = off + inc - v;
    if (threadIdx.x == SCAN_B - 1) g_bsum[blockIdx.x] = off + inc;
}

// finalize scan: each block sums its own prefix of the 98 block totals
__global__ void k_scanC() {
    __shared__ int wsum[SCAN_B / 32];
    int lane = threadIdx.x & 31, wid = threadIdx.x >> 5;
    int acc = 0;
    for (int j = threadIdx.x; j < blockIdx.x; j += SCAN_B) acc += g_bsum[j];
    #pragma unroll
    for (int o = 16; o; o >>= 1) acc += __shfl_xor_sync(~0u, acc, o);
    if (lane == 0) wsum[wid] = acc;
    __syncthreads();
    if (threadIdx.x == 0) {
        int s = 0;
        #pragma unroll
        for (int w = 0; w < SCAN_B / 32; w++) s += wsum[w];
        wsum[0] = s;
    }
    __syncthreads();
    int off = wsum[0];
    int i = blockIdx.x * SCAN_B + threadIdx.x;
    if (i < N_NODE) {
        int s = g_start[i] + off;
        g_start[i] = s;
        g_pos[i] = s;
    }
}

__global__ void k_scatter(const int* __restrict__ ei) {
    int e = blockIdx.x * blockDim.x + threadIdx.x;
    if (e >= N_EDGE) return;
    int r = ei[e];
    int p = atomicAdd(&g_pos[r], 1);
    g_csrcol[p] = ei[N_EDGE + e];
}

// ---------------- per-layer kernels ----------------

// warp per row, 2 edges in flight (one per 16-lane half).
// In-loop butterflies use HALF masks: trip counts are uniform within each
// half (all 16 lanes share the same i sequence) but can differ BETWEEN
// halves for odd n — a full-mask shuffle there deadlocks (R8/R9 bug).
__global__ void k_simrow(const float* __restrict__ feat) {
    int t = blockIdx.x * blockDim.x + threadIdx.x;
    int u = t >> 5, lane = t & 31;
    if (u >= N_NODE) return;
    int sub = lane >> 4, q = lane & 15;
    unsigned hmask = sub ? 0xFFFF0000u : 0x0000FFFFu;
    int st = g_start[u], n = g_hist[u];
    const float4* f4 = (const float4*)feat;
    float4 a = f4[u * 16 + q];          // row features: loaded ONCE per row
    float ir = g_inv[u];
    float rs = 0.f, k = 0.f;
    for (int i = sub; i < n; i += 2) {
        int c = g_csrcol[st + i];
        float4 b = f4[c * 16 + q];
        float s = a.x * b.x + a.y * b.y + a.z * b.z + a.w * b.w;
        s += __shfl_xor_sync(hmask, s, 8);
        s += __shfl_xor_sync(hmask, s, 4);
        s += __shfl_xor_sync(hmask, s, 2);
        s += __shfl_xor_sync(hmask, s, 1);
        s *= ir * g_inv[c];
        if (s < 0.1f) s = 0.f;
        if (q == 0) {
            g_simc[st + i] = s;
            rs += s;
            if (s > 0.f) k += 1.f;
        }
    }
    // reconverged: full-warp reduction is safe here
    #pragma unroll
    for (int o = 16; o; o >>= 1) {
        rs += __shfl_xor_sync(~0u, rs, o);
        k  += __shfl_xor_sync(~0u, k, o);
    }
    __syncwarp();                        // order sim stores before re-reads
    float wself = expf(1.f / (k + 1.f));
    float inv_rs = 1.f / fmaxf(rs, 1e-12f);
    float degw = 0.f;
    for (int i = lane; i < n; i += 32) {
        float s = g_simc[st + i];
        float w = (s > 0.f) ? expf(s * inv_rs) : 0.f;
        g_w[st + i] = w;
        degw += w;
    }
    #pragma unroll
    for (int o = 16; o; o >>= 1) degw += __shfl_xor_sync(~0u, degw, o);
    if (lane == 0) {
        float di = rsqrtf(fmaxf(degw + wself, 1e-12f));
        g_dinv[u] = di;
        g_selfc[u] = wself * di * di;
    }
}

// GEMM: Y[N, FOUT] = X[N, 64] @ W[64, FOUT]
template <int FOUT, int NPB>
__global__ void k_gemm(const float* __restrict__ X, const float* __restrict__ W,
                       float* __restrict__ Y) {
    constexpr int Q = FOUT / 4;
    __shared__ float4 sW[64 * Q];
    __shared__ float  sX[NPB * 64];
    int tid = threadIdx.x;
    const float4* W4 = (const float4*)W;
    for (int i = tid; i < 64 * Q; i += blockDim.x) sW[i] = W4[i];
    int base = blockIdx.x * NPB;
    for (int i = tid; i < NPB * 64; i += blockDim.x) {
        int n = base + i / 64;
        sX[i] = (n < N_NODE) ? X[n * 64 + (i & 63)] : 0.f;
    }
    __syncthreads();
    int ni = tid / Q, q = tid - ni * Q;
    int n = base + ni;
    if (n >= N_NODE) return;
    float4 acc = {0.f, 0.f, 0.f, 0.f};
    #pragma unroll
    for (int k = 0; k < 64; k++) {
        float xv = sX[ni * 64 + k];
        float4 w = sW[k * Q + q];
        acc.x += xv * w.x; acc.y += xv * w.y;
        acc.z += xv * w.z; acc.w += xv * w.w;
    }
    ((float4*)Y)[n * Q + q] = acc;
}

// layer-1 aggregate, warp per row, 2 edges in flight; fused relu + h-norm
// epilogue. Shuffles only AFTER the loop (reconverged) — divergence-safe.
__global__ void k_agg1(const float* __restrict__ b1) {
    int t = blockIdx.x * blockDim.x + threadIdx.x;
    int u = t >> 5, lane = t & 31;
    if (u >= N_NODE) return;
    int sub = lane >> 4, q = lane & 15;
    int st = g_start[u], n = g_hist[u];
    const float4* H4 = (const float4*)g_xw;
    float4 acc = {0.f, 0.f, 0.f, 0.f};
    for (int i = sub; i < n; i += 2) {
        int p = st + i;
        float w = g_w[p];
        if (w != 0.f) {
            int c = g_csrcol[p];
            float coef = w * g_dinv[c];
            float4 v = H4[c * 16 + q];
            acc.x += coef * v.x; acc.y += coef * v.y;
            acc.z += coef * v.z; acc.w += coef * v.w;
        }
    }
    acc.x += __shfl_xor_sync(~0u, acc.x, 16);
    acc.y += __shfl_xor_sync(~0u, acc.y, 16);
    acc.z += __shfl_xor_sync(~0u, acc.z, 16);
    acc.w += __shfl_xor_sync(~0u, acc.w, 16);
    float dr = g_dinv[u], sc = g_selfc[u];
    float4 self = H4[u * 16 + q];
    float4 bq = ((const float4*)b1)[q];
    float4 o;
    o.x = fmaxf(dr * acc.x + sc * self.x + bq.x, 0.f);
    o.y = fmaxf(dr * acc.y + sc * self.y + bq.y, 0.f);
    o.z = fmaxf(dr * acc.z + sc * self.z + bq.z, 0.f);
    o.w = fmaxf(dr * acc.w + sc * self.w + bq.w, 0.f);
    if (lane < 16) ((float4*)g_h)[u * 16 + q] = o;
    // inv-norm of h for layer-2 attention (reduce over the 16-lane group)
    float s = o.x * o.x + o.y * o.y + o.z * o.z + o.w * o.w;
    s += __shfl_xor_sync(~0u, s, 8);
    s += __shfl_xor_sync(~0u, s, 4);
    s += __shfl_xor_sync(~0u, s, 2);
    s += __shfl_xor_sync(~0u, s, 1);
    if (lane == 0) g_inv[u] = 1.f / fmaxf(sqrtf(s), 1e-12f);
}

// layer-2 aggregate, warp per row; fused log-softmax epilogue
__global__ void k_agg2(const float* __restrict__ b2, float* __restrict__ O) {
    int t = blockIdx.x * blockDim.x + threadIdx.x;
    int u = t >> 5, lane = t & 31;
    if (u >= N_NODE) return;
    int sub = lane >> 4, q = lane & 15;
    bool act = q < 10;
    int st = g_start[u], n = g_hist[u];
    const float4* H4 = (const float4*)g_hw;
    float4 acc = {0.f, 0.f, 0.f, 0.f};
    for (int i = sub; i < n; i += 2) {
        int p = st + i;
        float w = g_w[p];
        if (w != 0.f && act) {
            int c = g_csrcol[p];
            float coef = w * g_dinv[c];
            float4 v = H4[c * 10 + q];
            acc.x += coef * v.x; acc.y += coef * v.y;
            acc.z += coef * v.z; acc.w += coef * v.w;
        }
    }
    acc.x += __shfl_xor_sync(~0u, acc.x, 16);
    acc.y += __shfl_xor_sync(~0u, acc.y, 16);
    acc.z += __shfl_xor_sync(~0u, acc.z, 16);
    acc.w += __shfl_xor_sync(~0u, acc.w, 16);
    float dr = g_dinv[u], sc = g_selfc[u];
    float4 o = {0.f, 0.f, 0.f, 0.f};
    if (act) {
        float4 self = H4[u * 10 + q];
        float4 bq = ((const float4*)b2)[q];
        o.x = dr * acc.x + sc * self.x + bq.x;
        o.y = dr * acc.y + sc * self.y + bq.y;
        o.z = dr * acc.z + sc * self.z + bq.z;
        o.w = dr * acc.w + sc * self.w + bq.w;
    }
    // log-softmax over 40 classes spread across the 10 active q-lanes
    float m = act ? fmaxf(fmaxf(o.x, o.y), fmaxf(o.z, o.w)) : -1e30f;
    m = fmaxf(m, __shfl_xor_sync(~0u, m, 8));
    m = fmaxf(m, __shfl_xor_sync(~0u, m, 4));
    m = fmaxf(m, __shfl_xor_sync(~0u, m, 2));
    m = fmaxf(m, __shfl_xor_sync(~0u, m, 1));
    float s = act ? (expf(o.x - m) + expf(o.y - m) + expf(o.z - m) + expf(o.w - m)) : 0.f;
    s += __shfl_xor_sync(~0u, s, 8);
    s += __shfl_xor_sync(~0u, s, 4);
    s += __shfl_xor_sync(~0u, s, 2);
    s += __shfl_xor_sync(~0u, s, 1);
    float lse = m + logf(s);
    if (lane < 16 && act) {
        float4 r = {o.x - lse, o.y - lse, o.z - lse, o.w - lse};
        ((float4*)O)[u * 10 + q] = r;
    }
}

// ---------------- launch (single stream — graph-capture safe) ----------------
extern "C" void kernel_launch(void* const* d_in, const int* in_sizes, int n_in,
                              void* d_out, int out_size) {
    const float* x  = (const float*)d_in[0];
    const int*   ei = (const int*)d_in[1];   // int32 (JAX default x64-disabled)
    const float* W1 = (const float*)d_in[2];
    const float* b1 = (const float*)d_in[3];
    const float* W2 = (const float*)d_in[4];
    const float* b2 = (const float*)d_in[5];
    float* out = (float*)d_out;

    float *p_h, *p_xw, *p_hw;
    cudaGetSymbolAddress((void**)&p_h,  g_h);
    cudaGetSymbolAddress((void**)&p_xw, g_xw);
    cudaGetSymbolAddress((void**)&p_hw, g_hw);

    const int T = 256;

    // ---- CSR build (int atomics only) ----
    k_prep<<<CDIV(N_NODE * 32, T), T>>>(x);
    k_hist<<<CDIV(N_EDGE, T), T>>>(ei);
    k_scanA<<<NBLK, SCAN_B>>>();
    k_scanC<<<NBLK, SCAN_B>>>();
    k_scatter<<<CDIV(N_EDGE, T), T>>>(ei);

    // ---- layer 1 (attention on x) ----
    k_simrow<<<CDIV(N_NODE * 32, T), T>>>(x);
    k_gemm<64, 16><<<CDIV(N_NODE, 16), 256>>>(x, W1, p_xw);
    k_agg1<<<CDIV(N_NODE * 32, T), T>>>(b1);

    // ---- layer 2 (attention on h) ----
    k_simrow<<<CDIV(N_NODE * 32, T), T>>>(p_h);
    k_gemm<40, 24><<<CDIV(N_NODE, 24), 240>>>(p_h, W2, p_hw);
    k_agg2<<<CDIV(N_NODE * 32, T), T>>>(b2, out);
}

// round 11
// speedup vs baseline: 1.3480x; 1.0742x over previous
#include <cuda_runtime.h>

#define N_NODE 50000
#define N_EDGE 800000
#define D 64
#define C 40
#define CDIV(a,b) (((a)+(b)-1)/(b))
#define SCAN_B 512
#define NBLK 98          // CDIV(N_NODE, SCAN_B)

// ---------------- scratch (static device arrays; no allocs) ----------------
__device__ __align__(16) float g_xw[N_NODE * D];   // x @ W1
__device__ __align__(16) float g_h[N_NODE * D];    // layer-1 output (post relu)
__device__ __align__(16) float g_hw[N_NODE * C];   // h @ W2
__device__ float g_inv[N_NODE];     // 1/max(||feat||,1e-12)
__device__ float g_dinv[N_NODE];    // 1/sqrt(deg_total)
__device__ float g_selfc[N_NODE];   // w_self * dinv^2
__device__ int   g_hist[N_NODE];    // per-row edge count
__device__ int   g_start[N_NODE];   // CSR row start (exclusive scan of hist)
__device__ int   g_pos[N_NODE];     // scatter cursor
__device__ int   g_bsum[NBLK];
__device__ int   g_csrcol[N_EDGE];  // col, CSR order
__device__ float g_simc[N_EDGE];    // sim, CSR order
__device__ float g_w[N_EDGE];       // w_edge, CSR order

// ---------------- CSR build ----------------

// warp per node: inv-norm of x; zero histogram
__global__ void k_prep(const float* __restrict__ feat) {
    int t = blockIdx.x * blockDim.x + threadIdx.x;
    int u = t >> 5, lane = t & 31;
    if (u >= N_NODE) return;
    float v0 = feat[u * D + lane];
    float v1 = feat[u * D + lane + 32];
    float s = v0 * v0 + v1 * v1;
    #pragma unroll
    for (int o = 16; o; o >>= 1) s += __shfl_xor_sync(~0u, s, o);
    if (lane == 0) {
        g_inv[u] = 1.f / fmaxf(sqrtf(s), 1e-12f);
        g_hist[u] = 0;
    }
}

__global__ void k_hist(const int* __restrict__ ei) {
    int e = blockIdx.x * blockDim.x + threadIdx.x;
    if (e < N_EDGE) atomicAdd(&g_hist[ei[e]], 1);
}

// block-level exclusive scan of hist (512/block), block totals to g_bsum
__global__ void k_scanA() {
    __shared__ int wsum[16];
    int i = blockIdx.x * SCAN_B + threadIdx.x;
    int lane = threadIdx.x & 31, wid = threadIdx.x >> 5;
    int v = (i < N_NODE) ? g_hist[i] : 0;
    int inc = v;
    #pragma unroll
    for (int o = 1; o < 32; o <<= 1) {
        int t = __shfl_up_sync(~0u, inc, o);
        if (lane >= o) inc += t;
    }
    if (lane == 31) wsum[wid] = inc;
    __syncthreads();
    if (wid == 0) {
        int s = (lane < 16) ? wsum[lane] : 0;
        #pragma unroll
        for (int o = 1; o < 16; o <<= 1) {
            int t = __shfl_up_sync(~0u, s, o);
            if (lane >= o) s += t;
        }
        if (lane < 16) wsum[lane] = s;
    }
    __syncthreads();
    int off = wid ? wsum[wid - 1] : 0;
    if (i < N_NODE) g_start[i] = off + inc - v;
    if (threadIdx.x == SCAN_B - 1) g_bsum[blockIdx.x] = off + inc;
}

// finalize scan: each block sums its own prefix of the 98 block totals
__global__ void k_scanC() {
    __shared__ int wsum[SCAN_B / 32];
    int lane = threadIdx.x & 31, wid = threadIdx.x >> 5;
    int acc = 0;
    for (int j = threadIdx.x; j < blockIdx.x; j += SCAN_B) acc += g_bsum[j];
    #pragma unroll
    for (int o = 16; o; o >>= 1) acc += __shfl_xor_sync(~0u, acc, o);
    if (lane == 0) wsum[wid] = acc;
    __syncthreads();
    if (threadIdx.x == 0) {
        int s = 0;
        #pragma unroll
        for (int w = 0; w < SCAN_B / 32; w++) s += wsum[w];
        wsum[0] = s;
    }
    __syncthreads();
    int off = wsum[0];
    int i = blockIdx.x * SCAN_B + threadIdx.x;
    if (i < N_NODE) {
        int s = g_start[i] + off;
        g_start[i] = s;
        g_pos[i] = s;
    }
}

__global__ void k_scatter(const int* __restrict__ ei) {
    int e = blockIdx.x * blockDim.x + threadIdx.x;
    if (e >= N_EDGE) return;
    int r = ei[e];
    int p = atomicAdd(&g_pos[r], 1);
    g_csrcol[p] = ei[N_EDGE + e];
}

// ---------------- per-layer kernels ----------------

// warp per row, 4 edges in flight (one per 8-lane group, 2 float4 each).
// In-loop butterflies use per-GROUP masks: trip counts are uniform within
// each 8-lane group but differ between groups when n % 4 != 0 — a wider
// mask there deadlocks (the R8/R9 bug class).
__global__ void k_simrow(const float* __restrict__ feat) {
    int t = blockIdx.x * blockDim.x + threadIdx.x;
    int u = t >> 5, lane = t & 31;
    if (u >= N_NODE) return;
    int sub = lane >> 3, q = lane & 7;
    unsigned hmask = 0xFFu << (sub * 8);
    int st = g_start[u], n = g_hist[u];
    const float4* f4 = (const float4*)feat;
    float4 a0 = f4[u * 16 + q];         // row features: loaded ONCE per row
    float4 a1 = f4[u * 16 + 8 + q];
    float ir = g_inv[u];
    float rs = 0.f, k = 0.f;
    for (int i = sub; i < n; i += 4) {
        int c = g_csrcol[st + i];
        float4 b0 = f4[c * 16 + q];
        float4 b1 = f4[c * 16 + 8 + q];
        float s = a0.x * b0.x + a0.y * b0.y + a0.z * b0.z + a0.w * b0.w
                + a1.x * b1.x + a1.y * b1.y + a1.z * b1.z + a1.w * b1.w;
        s += __shfl_xor_sync(hmask, s, 4);
        s += __shfl_xor_sync(hmask, s, 2);
        s += __shfl_xor_sync(hmask, s, 1);
        s *= ir * g_inv[c];
        if (s < 0.1f) s = 0.f;
        if (q == 0) {
            g_simc[st + i] = s;
            rs += s;
            if (s > 0.f) k += 1.f;
        }
    }
    // reconverged: full-warp reduction is safe here
    #pragma unroll
    for (int o = 16; o; o >>= 1) {
        rs += __shfl_xor_sync(~0u, rs, o);
        k  += __shfl_xor_sync(~0u, k, o);
    }
    __syncwarp();                        // order sim stores before re-reads
    float wself = expf(1.f / (k + 1.f));
    float inv_rs = 1.f / fmaxf(rs, 1e-12f);
    float degw = 0.f;
    for (int i = lane; i < n; i += 32) {
        float s = g_simc[st + i];
        float w = (s > 0.f) ? expf(s * inv_rs) : 0.f;
        g_w[st + i] = w;
        degw += w;
    }
    #pragma unroll
    for (int o = 16; o; o >>= 1) degw += __shfl_xor_sync(~0u, degw, o);
    if (lane == 0) {
        float di = rsqrtf(fmaxf(degw + wself, 1e-12f));
        g_dinv[u] = di;
        g_selfc[u] = wself * di * di;
    }
}

// GEMM: Y[N, FOUT] = X[N, 64] @ W[64, FOUT]
template <int FOUT, int NPB>
__global__ void k_gemm(const float* __restrict__ X, const float* __restrict__ W,
                       float* __restrict__ Y) {
    constexpr int Q = FOUT / 4;
    __shared__ float4 sW[64 * Q];
    __shared__ float  sX[NPB * 64];
    int tid = threadIdx.x;
    const float4* W4 = (const float4*)W;
    for (int i = tid; i < 64 * Q; i += blockDim.x) sW[i] = W4[i];
    int base = blockIdx.x * NPB;
    for (int i = tid; i < NPB * 64; i += blockDim.x) {
        int n = base + i / 64;
        sX[i] = (n < N_NODE) ? X[n * 64 + (i & 63)] : 0.f;
    }
    __syncthreads();
    int ni = tid / Q, q = tid - ni * Q;
    int n = base + ni;
    if (n >= N_NODE) return;
    float4 acc = {0.f, 0.f, 0.f, 0.f};
    #pragma unroll
    for (int k = 0; k < 64; k++) {
        float xv = sX[ni * 64 + k];
        float4 w = sW[k * Q + q];
        acc.x += xv * w.x; acc.y += xv * w.y;
        acc.z += xv * w.z; acc.w += xv * w.w;
    }
    ((float4*)Y)[n * Q + q] = acc;
}

// layer-1 aggregate, warp per row, 2 edges in flight; fused relu + h-norm
// epilogue. Shuffles only AFTER the loop (reconverged) — divergence-safe.
__global__ void k_agg1(const float* __restrict__ b1) {
    int t = blockIdx.x * blockDim.x + threadIdx.x;
    int u = t >> 5, lane = t & 31;
    if (u >= N_NODE) return;
    int sub = lane >> 4, q = lane & 15;
    int st = g_start[u], n = g_hist[u];
    const float4* H4 = (const float4*)g_xw;
    float4 acc = {0.f, 0.f, 0.f, 0.f};
    for (int i = sub; i < n; i += 2) {
        int p = st + i;
        float w = g_w[p];
        if (w != 0.f) {
            int c = g_csrcol[p];
            float coef = w * g_dinv[c];
            float4 v = H4[c * 16 + q];
            acc.x += coef * v.x; acc.y += coef * v.y;
            acc.z += coef * v.z; acc.w += coef * v.w;
        }
    }
    acc.x += __shfl_xor_sync(~0u, acc.x, 16);
    acc.y += __shfl_xor_sync(~0u, acc.y, 16);
    acc.z += __shfl_xor_sync(~0u, acc.z, 16);
    acc.w += __shfl_xor_sync(~0u, acc.w, 16);
    float dr = g_dinv[u], sc = g_selfc[u];
    float4 self = H4[u * 16 + q];
    float4 bq = ((const float4*)b1)[q];
    float4 o;
    o.x = fmaxf(dr * acc.x + sc * self.x + bq.x, 0.f);
    o.y = fmaxf(dr * acc.y + sc * self.y + bq.y, 0.f);
    o.z = fmaxf(dr * acc.z + sc * self.z + bq.z, 0.f);
    o.w = fmaxf(dr * acc.w + sc * self.w + bq.w, 0.f);
    if (lane < 16) ((float4*)g_h)[u * 16 + q] = o;
    // inv-norm of h for layer-2 attention (reduce over the 16-lane group)
    float s = o.x * o.x + o.y * o.y + o.z * o.z + o.w * o.w;
    s += __shfl_xor_sync(~0u, s, 8);
    s += __shfl_xor_sync(~0u, s, 4);
    s += __shfl_xor_sync(~0u, s, 2);
    s += __shfl_xor_sync(~0u, s, 1);
    if (lane == 0) g_inv[u] = 1.f / fmaxf(sqrtf(s), 1e-12f);
}

// layer-2 aggregate, warp per row; fused log-softmax epilogue
__global__ void k_agg2(const float* __restrict__ b2, float* __restrict__ O) {
    int t = blockIdx.x * blockDim.x + threadIdx.x;
    int u = t >> 5, lane = t & 31;
    if (u >= N_NODE) return;
    int sub = lane >> 4, q = lane & 15;
    bool act = q < 10;
    int st = g_start[u], n = g_hist[u];
    const float4* H4 = (const float4*)g_hw;
    float4 acc = {0.f, 0.f, 0.f, 0.f};
    for (int i = sub; i < n; i += 2) {
        int p = st + i;
        float w = g_w[p];
        if (w != 0.f && act) {
            int c = g_csrcol[p];
            float coef = w * g_dinv[c];
            float4 v = H4[c * 10 + q];
            acc.x += coef * v.x; acc.y += coef * v.y;
            acc.z += coef * v.z; acc.w += coef * v.w;
        }
    }
    acc.x += __shfl_xor_sync(~0u, acc.x, 16);
    acc.y += __shfl_xor_sync(~0u, acc.y, 16);
    acc.z += __shfl_xor_sync(~0u, acc.z, 16);
    acc.w += __shfl_xor_sync(~0u, acc.w, 16);
    float dr = g_dinv[u], sc = g_selfc[u];
    float4 o = {0.f, 0.f, 0.f, 0.f};
    if (act) {
        float4 self = H4[u * 10 + q];
        float4 bq = ((const float4*)b2)[q];
        o.x = dr * acc.x + sc * self.x + bq.x;
        o.y = dr * acc.y + sc * self.y + bq.y;
        o.z = dr * acc.z + sc * self.z + bq.z;
        o.w = dr * acc.w + sc * self.w + bq.w;
    }
    // log-softmax over 40 classes spread across the 10 active q-lanes
    float m = act ? fmaxf(fmaxf(o.x, o.y), fmaxf(o.z, o.w)) : -1e30f;
    m = fmaxf(m, __shfl_xor_sync(~0u, m, 8));
    m = fmaxf(m, __shfl_xor_sync(~0u, m, 4));
    m = fmaxf(m, __shfl_xor_sync(~0u, m, 2));
    m = fmaxf(m, __shfl_xor_sync(~0u, m, 1));
    float s = act ? (expf(o.x - m) + expf(o.y - m) + expf(o.z - m) + expf(o.w - m)) : 0.f;
    s += __shfl_xor_sync(~0u, s, 8);
    s += __shfl_xor_sync(~0u, s, 4);
    s += __shfl_xor_sync(~0u, s, 2);
    s += __shfl_xor_sync(~0u, s, 1);
    float lse = m + logf(s);
    if (lane < 16 && act) {
        float4 r = {o.x - lse, o.y - lse, o.z - lse, o.w - lse};
        ((float4*)O)[u * 10 + q] = r;
    }
}

// ---------------- launch ----------------
extern "C" void kernel_launch(void* const* d_in, const int* in_sizes, int n_in,
                              void* d_out, int out_size) {
    const float* x  = (const float*)d_in[0];
    const int*   ei = (const int*)d_in[1];   // int32 (JAX default x64-disabled)
    const float* W1 = (const float*)d_in[2];
    const float* b1 = (const float*)d_in[3];
    const float* W2 = (const float*)d_in[4];
    const float* b2 = (const float*)d_in[5];
    float* out = (float*)d_out;

    float *p_h, *p_xw, *p_hw;
    cudaGetSymbolAddress((void**)&p_h,  g_h);
    cudaGetSymbolAddress((void**)&p_xw, g_xw);
    cudaGetSymbolAddress((void**)&p_hw, g_hw);

    // Side stream for the GEMMs (no data dependence on the attention chain).
    // Event fork/join from the capture stream is the documented capture
    // pattern; the R8 timeout was the simrow shuffle deadlock (proved by R9
    // reproducing it stream-free), not this.
    cudaStream_t s2;
    cudaStreamCreateWithFlags(&s2, cudaStreamNonBlocking);
    cudaEvent_t evF1, evG1, evF2, evG2;
    cudaEventCreateWithFlags(&evF1, cudaEventDisableTiming);
    cudaEventCreateWithFlags(&evG1, cudaEventDisableTiming);
    cudaEventCreateWithFlags(&evF2, cudaEventDisableTiming);
    cudaEventCreateWithFlags(&evG2, cudaEventDisableTiming);

    const int T = 256;

    // fork: gemm1 depends only on x/W1 — runs under the CSR+sim chain
    cudaEventRecord(evF1, 0);
    cudaStreamWaitEvent(s2, evF1, 0);
    k_gemm<64, 16><<<CDIV(N_NODE, 16), 256, 0, s2>>>(x, W1, p_xw);
    cudaEventRecord(evG1, s2);

    // ---- CSR build (int atomics only) ----
    k_prep<<<CDIV(N_NODE * 32, T), T>>>(x);
    k_hist<<<CDIV(N_EDGE, T), T>>>(ei);
    k_scanA<<<NBLK, SCAN_B>>>();
    k_scanC<<<NBLK, SCAN_B>>>();
    k_scatter<<<CDIV(N_EDGE, T), T>>>(ei);

    // ---- layer 1 (attention on x) ----
    k_simrow<<<CDIV(N_NODE * 32, T), T>>>(x);
    cudaStreamWaitEvent(0, evG1, 0);
    k_agg1<<<CDIV(N_NODE * 32, T), T>>>(b1);

    // fork: gemm2 needs only h — overlaps simrow2
    cudaEventRecord(evF2, 0);
    cudaStreamWaitEvent(s2, evF2, 0);
    k_gemm<40, 24><<<CDIV(N_NODE, 24), 240, 0, s2>>>(p_h, W2, p_hw);
    cudaEventRecord(evG2, s2);

    // ---- layer 2 (attention on h) ----
    k_simrow<<<CDIV(N_NODE * 32, T), T>>>(p_h);
    cudaStreamWaitEvent(0, evG2, 0);
    k_agg2<<<CDIV(N_NODE * 32, T), T>>>(b2, out);
}

// round 12
// speedup vs baseline: 1.3733x; 1.0188x over previous
#include <cuda_runtime.h>

#define N_NODE 50000
#define N_EDGE 800000
#define D 64
#define C 40
#define CDIV(a,b) (((a)+(b)-1)/(b))
#define SCAN_B 512
#define NBLK 98          // CDIV(N_NODE, SCAN_B)

// ---------------- scratch (static device arrays; no allocs) ----------------
__device__ __align__(16) float g_xw[N_NODE * D];   // x @ W1
__device__ __align__(16) float g_h[N_NODE * D];    // layer-1 output (post relu)
__device__ __align__(16) float g_hw[N_NODE * C];   // h @ W2
__device__ float g_inv[N_NODE];     // 1/max(||feat||,1e-12)
__device__ float g_dinv[N_NODE];    // 1/sqrt(deg_total)
__device__ float g_selfc[N_NODE];   // w_self * dinv^2
__device__ int   g_hist[N_NODE];    // per-row edge count
__device__ int   g_start[N_NODE];   // CSR row start
__device__ int   g_pos[N_NODE];     // scatter cursor, then compacted count
__device__ int   g_flag[NBLK];      // scan lookback flags (total+1; 0 = not ready)
__device__ int   g_csrcol[N_EDGE];  // col, CSR order (full)
__device__ int   g_ccol[N_EDGE];    // col, compacted survivors per row
__device__ float g_simc[N_EDGE];    // sim, CSR order
__device__ float g_w[N_EDGE];       // w_edge, compacted survivors per row

// ---------------- CSR build ----------------

__global__ void k_zero() {
    int i = blockIdx.x * blockDim.x + threadIdx.x;
    if (i < N_NODE) g_hist[i] = 0;
    if (i < NBLK) g_flag[i] = 0;
}

// warp per node: inv-norm of features (off critical path, side stream)
__global__ void k_prep(const float* __restrict__ feat) {
    int t = blockIdx.x * blockDim.x + threadIdx.x;
    int u = t >> 5, lane = t & 31;
    if (u >= N_NODE) return;
    float v0 = feat[u * D + lane];
    float v1 = feat[u * D + lane + 32];
    float s = v0 * v0 + v1 * v1;
    #pragma unroll
    for (int o = 16; o; o >>= 1) s += __shfl_xor_sync(~0u, s, o);
    if (lane == 0) g_inv[u] = 1.f / fmaxf(sqrtf(s), 1e-12f);
}

__global__ void k_hist(const int* __restrict__ ei) {
    int e = blockIdx.x * blockDim.x + threadIdx.x;
    if (e < N_EDGE) atomicAdd(&g_hist[ei[e]], 1);
}

// single-pass exclusive scan: local block scan, publish total+1, parallel
// lookback over predecessor totals. All 98 blocks are co-resident (148 SMs)
// so the spin always makes progress.
__global__ void k_scan() {
    __shared__ int wsum[16];
    __shared__ int xsum[16];
    __shared__ int s_off;
    int i = blockIdx.x * SCAN_B + threadIdx.x;
    int lane = threadIdx.x & 31, wid = threadIdx.x >> 5;
    int v = (i < N_NODE) ? g_hist[i] : 0;
    int inc = v;
    #pragma unroll
    for (int o = 1; o < 32; o <<= 1) {
        int t = __shfl_up_sync(~0u, inc, o);
        if (lane >= o) inc += t;
    }
    if (lane == 31) wsum[wid] = inc;
    __syncthreads();
    if (wid == 0) {
        int s = (lane < 16) ? wsum[lane] : 0;
        #pragma unroll
        for (int o = 1; o < 16; o <<= 1) {
            int t = __shfl_up_sync(~0u, s, o);
            if (lane >= o) s += t;
        }
        if (lane < 16) wsum[lane] = s;
    }
    __syncthreads();
    int woff = wid ? wsum[wid - 1] : 0;
    int total = wsum[15];
    if (threadIdx.x == 0) {
        __threadfence();
        atomicExch(&g_flag[blockIdx.x], total + 1);
    }
    // lookback: thread j spins on predecessor j's total (<=97 predecessors)
    int acc = 0;
    if (threadIdx.x < blockIdx.x) {
        int p;
        while ((p = *(volatile int*)&g_flag[threadIdx.x]) == 0) {}
        acc = p - 1;
    }
    #pragma unroll
    for (int o = 16; o; o >>= 1) acc += __shfl_xor_sync(~0u, acc, o);
    if (lane == 0) xsum[wid] = acc;
    __syncthreads();
    if (threadIdx.x == 0) {
        int s = 0;
        #pragma unroll
        for (int w = 0; w < 16; w++) s += xsum[w];
        s_off = s;
    }
    __syncthreads();
    if (i < N_NODE) {
        int s = s_off + woff + inc - v;
        g_start[i] = s;
        g_pos[i] = s;
    }
}

__global__ void k_scatter(const int* __restrict__ ei) {
    int e = blockIdx.x * blockDim.x + threadIdx.x;
    if (e >= N_EDGE) return;
    int r = ei[e];
    int p = atomicAdd(&g_pos[r], 1);
    g_csrcol[p] = ei[N_EDGE + e];
}

// ---------------- per-layer kernels ----------------

// warp per row. Pass 1: 4 edges in flight (8-lane groups, 2 float4/lane),
// per-GROUP shuffle masks (trip counts differ between groups — wider mask
// deadlocks). Pass 2: w_edge + ballot-compaction of survivors into
// g_ccol/g_w dense prefixes; count -> g_pos[u].
__global__ void k_simrow(const float* __restrict__ feat) {
    int t = blockIdx.x * blockDim.x + threadIdx.x;
    int u = t >> 5, lane = t & 31;
    if (u >= N_NODE) return;
    int sub = lane >> 3, q = lane & 7;
    unsigned hmask = 0xFFu << (sub * 8);
    int st = g_start[u], n = g_hist[u];
    const float4* f4 = (const float4*)feat;
    float4 a0 = f4[u * 16 + q];
    float4 a1 = f4[u * 16 + 8 + q];
    float ir = g_inv[u];
    float rs = 0.f, k = 0.f;
    for (int i = sub; i < n; i += 4) {
        int c = g_csrcol[st + i];
        float4 b0 = f4[c * 16 + q];
        float4 b1v = f4[c * 16 + 8 + q];
        float s = a0.x * b0.x + a0.y * b0.y + a0.z * b0.z + a0.w * b0.w
                + a1.x * b1v.x + a1.y * b1v.y + a1.z * b1v.z + a1.w * b1v.w;
        s += __shfl_xor_sync(hmask, s, 4);
        s += __shfl_xor_sync(hmask, s, 2);
        s += __shfl_xor_sync(hmask, s, 1);
        s *= ir * g_inv[c];
        if (s < 0.1f) s = 0.f;
        if (q == 0) {
            g_simc[st + i] = s;
            rs += s;
            if (s > 0.f) k += 1.f;
        }
    }
    #pragma unroll
    for (int o = 16; o; o >>= 1) {
        rs += __shfl_xor_sync(~0u, rs, o);
        k  += __shfl_xor_sync(~0u, k, o);
    }
    __syncwarp();                        // order sim stores before re-reads
    float wself = expf(1.f / (k + 1.f));
    float inv_rs = 1.f / fmaxf(rs, 1e-12f);
    float degw = 0.f;
    int base = 0;
    for (int i0 = 0; i0 < n; i0 += 32) {  // uniform trip count: full-mask safe
        int i = i0 + lane;
        float s = (i < n) ? g_simc[st + i] : 0.f;
        float w = (s > 0.f) ? expf(s * inv_rs) : 0.f;
        degw += w;
        unsigned m = __ballot_sync(~0u, w > 0.f);
        if (w > 0.f) {
            int idx = base + __popc(m & ((1u << lane) - 1u));
            g_ccol[st + idx] = g_csrcol[st + i];
            g_w[st + idx] = w;
        }
        base += __popc(m);
    }
    #pragma unroll
    for (int o = 16; o; o >>= 1) degw += __shfl_xor_sync(~0u, degw, o);
    if (lane == 0) {
        float di = rsqrtf(fmaxf(degw + wself, 1e-12f));
        g_dinv[u] = di;
        g_selfc[u] = wself * di * di;
        g_pos[u] = base;                 // compacted survivor count
    }
}

// GEMM: Y[N, FOUT] = X[N, 64] @ W[64, FOUT]
template <int FOUT, int NPB>
__global__ void k_gemm(const float* __restrict__ X, const float* __restrict__ W,
                       float* __restrict__ Y) {
    constexpr int Q = FOUT / 4;
    __shared__ float4 sW[64 * Q];
    __shared__ float  sX[NPB * 64];
    int tid = threadIdx.x;
    const float4* W4 = (const float4*)W;
    for (int i = tid; i < 64 * Q; i += blockDim.x) sW[i] = W4[i];
    int base = blockIdx.x * NPB;
    for (int i = tid; i < NPB * 64; i += blockDim.x) {
        int n = base + i / 64;
        sX[i] = (n < N_NODE) ? X[n * 64 + (i & 63)] : 0.f;
    }
    __syncthreads();
    int ni = tid / Q, q = tid - ni * Q;
    int n = base + ni;
    if (n >= N_NODE) return;
    float4 acc = {0.f, 0.f, 0.f, 0.f};
    #pragma unroll
    for (int k = 0; k < 64; k++) {
        float xv = sX[ni * 64 + k];
        float4 w = sW[k * Q + q];
        acc.x += xv * w.x; acc.y += xv * w.y;
        acc.z += xv * w.z; acc.w += xv * w.w;
    }
    ((float4*)Y)[n * Q + q] = acc;
}

// layer-1 aggregate: dense compacted edges, 4 in flight (8-lane groups,
// 2 float4/lane). No in-loop shuffles; cross-sub reduction after the loop.
// Fused relu + h-norm epilogue.
__global__ void k_agg1(const float* __restrict__ b1) {
    int t = blockIdx.x * blockDim.x + threadIdx.x;
    int u = t >> 5, lane = t & 31;
    if (u >= N_NODE) return;
    int sub = lane >> 3, q = lane & 7;
    int st = g_start[u], n2 = g_pos[u];
    const float4* H4 = (const float4*)g_xw;
    float4 acc0 = {0.f, 0.f, 0.f, 0.f};
    float4 acc1 = {0.f, 0.f, 0.f, 0.f};
    for (int i = sub; i < n2; i += 4) {
        int c = g_ccol[st + i];
        float coef = g_w[st + i] * g_dinv[c];
        float4 v0 = H4[c * 16 + q];
        float4 v1 = H4[c * 16 + 8 + q];
        acc0.x += coef * v0.x; acc0.y += coef * v0.y;
        acc0.z += coef * v0.z; acc0.w += coef * v0.w;
        acc1.x += coef * v1.x; acc1.y += coef * v1.y;
        acc1.z += coef * v1.z; acc1.w += coef * v1.w;
    }
    // reduce across the 4 sub-groups (reconverged: full mask safe)
    #pragma unroll
    for (int o = 8; o <= 16; o <<= 1) {
        acc0.x += __shfl_xor_sync(~0u, acc0.x, o);
        acc0.y += __shfl_xor_sync(~0u, acc0.y, o);
        acc0.z += __shfl_xor_sync(~0u, acc0.z, o);
        acc0.w += __shfl_xor_sync(~0u, acc0.w, o);
        acc1.x += __shfl_xor_sync(~0u, acc1.x, o);
        acc1.y += __shfl_xor_sync(~0u, acc1.y, o);
        acc1.z += __shfl_xor_sync(~0u, acc1.z, o);
        acc1.w += __shfl_xor_sync(~0u, acc1.w, o);
    }
    int f4i = lane & 15;                 // float4 index this lane finalizes
    float4 accv = (lane & 8) ? acc1 : acc0;
    float dr = g_dinv[u], sc = g_selfc[u];
    float4 self = H4[u * 16 + f4i];
    float4 bq = ((const float4*)b1)[f4i];
    float4 o;
    o.x = fmaxf(dr * accv.x + sc * self.x + bq.x, 0.f);
    o.y = fmaxf(dr * accv.y + sc * self.y + bq.y, 0.f);
    o.z = fmaxf(dr * accv.z + sc * self.z + bq.z, 0.f);
    o.w = fmaxf(dr * accv.w + sc * self.w + bq.w, 0.f);
    if (lane < 16) ((float4*)g_h)[u * 16 + f4i] = o;
    // inv-norm of h (offsets 8,4,2,1 keep lanes 16-31 in their own halves)
    float s = o.x * o.x + o.y * o.y + o.z * o.z + o.w * o.w;
    s += __shfl_xor_sync(~0u, s, 8);
    s += __shfl_xor_sync(~0u, s, 4);
    s += __shfl_xor_sync(~0u, s, 2);
    s += __shfl_xor_sync(~0u, s, 1);
    if (lane == 0) g_inv[u] = 1.f / fmaxf(sqrtf(s), 1e-12f);
}

// layer-2 aggregate: dense compacted edges, 2 in flight; fused log-softmax
__global__ void k_agg2(const float* __restrict__ b2, float* __restrict__ O) {
    int t = blockIdx.x * blockDim.x + threadIdx.x;
    int u = t >> 5, lane = t & 31;
    if (u >= N_NODE) return;
    int sub = lane >> 4, q = lane & 15;
    bool act = q < 10;
    int st = g_start[u], n2 = g_pos[u];
    const float4* H4 = (const float4*)g_hw;
    float4 acc = {0.f, 0.f, 0.f, 0.f};
    for (int i = sub; i < n2; i += 2) {
        int p = st + i;
        int c = g_ccol[p];
        float coef = g_w[p] * g_dinv[c];
        if (act) {
            float4 v = H4[c * 10 + q];
            acc.x += coef * v.x; acc.y += coef * v.y;
            acc.z += coef * v.z; acc.w += coef * v.w;
        }
    }
    acc.x += __shfl_xor_sync(~0u, acc.x, 16);
    acc.y += __shfl_xor_sync(~0u, acc.y, 16);
    acc.z += __shfl_xor_sync(~0u, acc.z, 16);
    acc.w += __shfl_xor_sync(~0u, acc.w, 16);
    float dr = g_dinv[u], sc = g_selfc[u];
    float4 o = {0.f, 0.f, 0.f, 0.f};
    if (act) {
        float4 self = H4[u * 10 + q];
        float4 bq = ((const float4*)b2)[q];
        o.x = dr * acc.x + sc * self.x + bq.x;
        o.y = dr * acc.y + sc * self.y + bq.y;
        o.z = dr * acc.z + sc * self.z + bq.z;
        o.w = dr * acc.w + sc * self.w + bq.w;
    }
    float m = act ? fmaxf(fmaxf(o.x, o.y), fmaxf(o.z, o.w)) : -1e30f;
    m = fmaxf(m, __shfl_xor_sync(~0u, m, 8));
    m = fmaxf(m, __shfl_xor_sync(~0u, m, 4));
    m = fmaxf(m, __shfl_xor_sync(~0u, m, 2));
    m = fmaxf(m, __shfl_xor_sync(~0u, m, 1));
    float s = act ? (expf(o.x - m) + expf(o.y - m) + expf(o.z - m) + expf(o.w - m)) : 0.f;
    s += __shfl_xor_sync(~0u, s, 8);
    s += __shfl_xor_sync(~0u, s, 4);
    s += __shfl_xor_sync(~0u, s, 2);
    s += __shfl_xor_sync(~0u, s, 1);
    float lse = m + logf(s);
    if (lane < 16 && act) {
        float4 r = {o.x - lse, o.y - lse, o.z - lse, o.w - lse};
        ((float4*)O)[u * 10 + q] = r;
    }
}

// ---------------- launch ----------------
extern "C" void kernel_launch(void* const* d_in, const int* in_sizes, int n_in,
                              void* d_out, int out_size) {
    const float* x  = (const float*)d_in[0];
    const int*   ei = (const int*)d_in[1];   // int32 (JAX default x64-disabled)
    const float* W1 = (const float*)d_in[2];
    const float* b1 = (const float*)d_in[3];
    const float* W2 = (const float*)d_in[4];
    const float* b2 = (const float*)d_in[5];
    float* out = (float*)d_out;

    float *p_h, *p_xw, *p_hw;
    cudaGetSymbolAddress((void**)&p_h,  g_h);
    cudaGetSymbolAddress((void**)&p_xw, g_xw);
    cudaGetSymbolAddress((void**)&p_hw, g_hw);

    cudaStream_t s2;
    cudaStreamCreateWithFlags(&s2, cudaStreamNonBlocking);
    cudaEvent_t evF0, evP, evG1, evF2, evG2;
    cudaEventCreateWithFlags(&evF0, cudaEventDisableTiming);
    cudaEventCreateWithFlags(&evP,  cudaEventDisableTiming);
    cudaEventCreateWithFlags(&evG1, cudaEventDisableTiming);
    cudaEventCreateWithFlags(&evF2, cudaEventDisableTiming);
    cudaEventCreateWithFlags(&evG2, cudaEventDisableTiming);

    const int T = 256;

    // side stream: prep (norms) then gemm1 — both independent of CSR chain
    cudaEventRecord(evF0, 0);
    cudaStreamWaitEvent(s2, evF0, 0);
    k_prep<<<CDIV(N_NODE * 32, T), T, 0, s2>>>(x);
    cudaEventRecord(evP, s2);
    k_gemm<64, 16><<<CDIV(N_NODE, 16), 256, 0, s2>>>(x, W1, p_xw);
    cudaEventRecord(evG1, s2);

    // ---- CSR build ----
    k_zero<<<CDIV(N_NODE, T), T>>>();
    k_hist<<<CDIV(N_EDGE, T), T>>>(ei);
    k_scan<<<NBLK, SCAN_B>>>();
    k_scatter<<<CDIV(N_EDGE, T), T>>>(ei);

    // ---- layer 1 ----
    cudaStreamWaitEvent(0, evP, 0);
    k_simrow<<<CDIV(N_NODE * 32, T), T>>>(x);
    cudaStreamWaitEvent(0, evG1, 0);
    k_agg1<<<CDIV(N_NODE * 32, T), T>>>(b1);

    // side stream: gemm2 (needs only h) overlaps simrow2
    cudaEventRecord(evF2, 0);
    cudaStreamWaitEvent(s2, evF2, 0);
    k_gemm<40, 24><<<CDIV(N_NODE, 24), 240, 0, s2>>>(p_h, W2, p_hw);
    cudaEventRecord(evG2, s2);

    // ---- layer 2 ----
    k_simrow<<<CDIV(N_NODE * 32, T), T>>>(p_h);
    cudaStreamWaitEvent(0, evG2, 0);
    k_agg2<<<CDIV(N_NODE * 32, T), T>>>(b2, out);
}